// round 14
// baseline (speedup 1.0000x reference)
#include <cuda_runtime.h>
#include <cuda_fp16.h>
#include <math.h>
#include <stdint.h>

#define NN 10000
#define NP 10176            // 106 * 96
#define EE 160000
#define HH 512
#define CC 10
#define MM (HH * HH)
#define BN_EPS 1e-5f

// ---------------- device scratch ----------------
__device__ float  g_part[NP * HH];   // fp32 partial (proj split only)
__device__ float  g_agg[NP * HH];    // fp32 BN'd agg for final layer
__device__ __half g_z1[NP * HH];     // raw relu z fp16 (ping)
__device__ __half g_z2[NP * HH];     // raw relu z fp16 (pong)
__device__ __half g_x16[NP * HH];    // x fp16
__device__ __half g_h16[NP * HH];    // BN(z) fp16 (root operand)
__device__ __half g_a16[NP * HH];    // agg fp16
__device__ __half g_w[8 * MM];       // weights fp16
__device__ float g_scale[NN];
__device__ int   g_degi[NN];         // zeroed per-node inside k_agg3
__device__ int   g_rowptr[NN + 1];
__device__ int   g_fill[NN];
__device__ int   g_esrc[EE];
__device__ float g_sum[HH];
__device__ float g_sq[HH];
__device__ float g_bnA[HH];
__device__ float g_bnB[HH];

// ---------------- PTX helpers ----------------
__device__ __forceinline__ uint32_t cvta_s(const void* p) {
    return (uint32_t)__cvta_generic_to_shared(p);
}
__device__ __forceinline__ void cpa16(uint32_t dst, const void* src) {
    asm volatile("cp.async.cg.shared.global [%0], [%1], 16;\n" :: "r"(dst), "l"(src));
}
__device__ __forceinline__ void ldm_x4(uint32_t& r0, uint32_t& r1, uint32_t& r2, uint32_t& r3, uint32_t addr) {
    asm volatile("ldmatrix.sync.aligned.m8n8.x4.shared.b16 {%0,%1,%2,%3}, [%4];\n"
                 : "=r"(r0), "=r"(r1), "=r"(r2), "=r"(r3) : "r"(addr));
}
__device__ __forceinline__ void mma_f16(float* d, uint32_t a0, uint32_t a1, uint32_t a2, uint32_t a3,
                                        uint32_t b0, uint32_t b1) {
    asm volatile("mma.sync.aligned.m16n8k16.row.col.f32.f16.f16.f32 "
                 "{%0,%1,%2,%3}, {%4,%5,%6,%7}, {%8,%9}, {%0,%1,%2,%3};\n"
                 : "+f"(d[0]), "+f"(d[1]), "+f"(d[2]), "+f"(d[3])
                 : "r"(a0), "r"(a1), "r"(a2), "r"(a3), "r"(b0), "r"(b1));
}

// ---------------- fused prep: pads, x round, weight round, stats zero --------
#define SPLITX (NN * HH)
#define SPLITW (8 * MM)
#define PADSZ  ((NP - NN) * HH)
#define PREP_TOTAL (SPLITX + SPLITW + PADSZ + HH)

__global__ void k_prep(const float* __restrict__ x,
                       const float* __restrict__ Wpr, const float* __restrict__ Wpw,
                       const float* __restrict__ Wrel, const float* __restrict__ Wroot) {
    int i = blockIdx.x * blockDim.x + threadIdx.x;
    if (i < SPLITX) {
        g_x16[i] = __float2half(x[i]);
        return;
    }
    i -= SPLITX;
    if (i < SPLITW) {
        int w = i >> 18;
        int off = i & (MM - 1);
        const float* src;
        if (w == 0) src = Wpr + off;
        else if (w == 1) src = Wpw + off;
        else if (w < 5) src = Wrel + (size_t)(w - 2) * MM + off;
        else src = Wroot + (size_t)(w - 5) * MM + off;
        g_w[i] = __float2half(*src);
        return;
    }
    i -= SPLITW;
    if (i < PADSZ) {
        int off = NN * HH + i;
        __half z = __float2half(0.0f);
        g_x16[off] = z;
        g_h16[off] = z;
        g_a16[off] = z;
        return;
    }
    i -= PADSZ;
    if (i < HH) { g_sum[i] = 0.f; g_sq[i] = 0.f; }
}

// ---------------- CSR build ----------------
__global__ void k_deg(const int* __restrict__ ei) {
    int e = blockIdx.x * blockDim.x + threadIdx.x;
    if (e < EE) atomicAdd(&g_degi[ei[EE + e]], 1);
}
__global__ void k_scanscale() {
    __shared__ int warp_part[32];
    __shared__ int carry;
    int t = threadIdx.x;
    int lane = t & 31, w = t >> 5;
    if (t == 0) carry = 0;
    __syncthreads();
    for (int base = 0; base < NN; base += 1024) {
        int i = base + t;
        int v = (i < NN) ? g_degi[i] : 0;
        if (i < NN) g_scale[i] = 1.0f / (float)(v > 0 ? v : 1);
        int s = v;
#pragma unroll
        for (int o = 1; o < 32; o <<= 1) {
            int u = __shfl_up_sync(0xffffffff, s, o);
            if (lane >= o) s += u;
        }
        if (lane == 31) warp_part[w] = s;
        __syncthreads();
        if (w == 0) {
            int p = warp_part[lane];
#pragma unroll
            for (int o = 1; o < 32; o <<= 1) {
                int u = __shfl_up_sync(0xffffffff, p, o);
                if (lane >= o) p += u;
            }
            warp_part[lane] = p;
        }
        __syncthreads();
        int add = (w > 0) ? warp_part[w - 1] : 0;
        int inc = s + add + carry;
        if (i < NN) g_rowptr[i + 1] = inc;
        __syncthreads();
        if (t == 1023) carry = inc;
        __syncthreads();
    }
    if (t == 0) g_rowptr[0] = 0;
}
__global__ void k_fill(const int* __restrict__ ei) {
    int e = blockIdx.x * blockDim.x + threadIdx.x;
    if (e < EE) {
        int dst = ei[EE + e];
        int pos = g_rowptr[dst] + atomicAdd(&g_fill[dst], 1);
        g_esrc[pos] = ei[e];
    }
}

// ---------------- fp16 mean aggregation + BN affine + fused own-row BN ----------------
// If ownbn != nullptr: also write h16[node] = bnA*z[node]+bnB (replaces k_bnapply).
__global__ void k_agg3(const __half* __restrict__ z, int useBN,
                       __half* __restrict__ oh, float* __restrict__ of,
                       __half* __restrict__ ownbn) {
    int node = blockIdx.x;
    int t = threadIdx.x;                   // 0..127, 4 halves each
    if (t == 0) { g_degi[node] = 0; g_fill[node] = 0; }   // reset for next replay
    int s = g_rowptr[node];
    int e = g_rowptr[node + 1];
    float ax = 0.f, ay = 0.f, az = 0.f, aw = 0.f;
    int j = s;
    for (; j + 1 < e; j += 2) {
        int s0 = g_esrc[j];
        int s1 = g_esrc[j + 1];
        uint2 r0 = ((const uint2*)(z + (size_t)s0 * HH))[t];
        uint2 r1 = ((const uint2*)(z + (size_t)s1 * HH))[t];
        float2 a0 = __half22float2(*(__half2*)&r0.x);
        float2 a1 = __half22float2(*(__half2*)&r0.y);
        float2 b0 = __half22float2(*(__half2*)&r1.x);
        float2 b1 = __half22float2(*(__half2*)&r1.y);
        ax += a0.x + b0.x; ay += a0.y + b0.y;
        az += a1.x + b1.x; aw += a1.y + b1.y;
    }
    if (j < e) {
        int s0 = g_esrc[j];
        uint2 r0 = ((const uint2*)(z + (size_t)s0 * HH))[t];
        float2 a0 = __half22float2(*(__half2*)&r0.x);
        float2 a1 = __half22float2(*(__half2*)&r0.y);
        ax += a0.x; ay += a0.y; az += a1.x; aw += a1.y;
    }
    float sc = g_scale[node];
    ax *= sc; ay *= sc; az *= sc; aw *= sc;
    float4 a, b;
    if (useBN) {
        a = ((const float4*)g_bnA)[t];
        b = ((const float4*)g_bnB)[t];
        ax = ax * a.x + b.x; ay = ay * a.y + b.y;
        az = az * a.z + b.z; aw = aw * a.w + b.w;
    }
    if (of) {
        ((float4*)(of + (size_t)node * HH))[t] = make_float4(ax, ay, az, aw);
    }
    if (oh) {
        __half2* ph = (__half2*)(oh + (size_t)node * HH);
        ph[t * 2 + 0] = __halves2half2(__float2half(ax), __float2half(ay));
        ph[t * 2 + 1] = __halves2half2(__float2half(az), __float2half(aw));
    }
    if (ownbn) {
        // fused bnapply: BN of this node's own z row
        uint2 raw = ((const uint2*)(z + (size_t)node * HH))[t];
        float2 v0 = __half22float2(*(__half2*)&raw.x);
        float2 v1 = __half22float2(*(__half2*)&raw.y);
        v0.x = v0.x * a.x + b.x;
        v0.y = v0.y * a.y + b.y;
        v1.x = v1.x * a.z + b.z;
        v1.y = v1.y * a.w + b.w;
        __half2* po = (__half2*)(ownbn + (size_t)node * HH);
        po[t * 2 + 0] = __halves2half2(__float2half(v0.x), __float2half(v0.y));
        po[t * 2 + 1] = __halves2half2(__float2half(v1.x), __float2half(v1.y));
    }
}

// ---------------- mma.sync dual GEMM, 96x64 tile, BK=32, fp16, high-occ ----------
// 6 warps: 3(M) x 2(N), warp tile 32x32 (acc 32 regs). 5 CTAs/SM.
// acc += A@W^T. nk=32: dual (A1,W1 kt<16; A2,W2 kt>=16). nk=16: single pair.
#define LDS 40
#define A_HALVES (96 * LDS)                       // 3840
#define B_HALVES (64 * LDS)                       // 2560
#define STAGE_HALVES (A_HALVES + B_HALVES)        // 6400 halves = 12800 B

__global__ __launch_bounds__(192, 5)
void k_gemm9(const __half* __restrict__ a1, const __half* __restrict__ a2,
             const __half* __restrict__ w1, const __half* __restrict__ w2,
             float* __restrict__ Cpart, const float* __restrict__ Cin,
             __half* __restrict__ Z,
             int nk, int finalize) {
    __shared__ __align__(16) __half dsm[2 * STAGE_HALVES];   // 25.6 KB

    const int tx = threadIdx.x;
    const int lane = tx & 31;
    const int warp = tx >> 5;            // 0..5
    const int wm = (warp % 3) * 32;
    const int wn = (warp / 3) * 32;
    const int m0 = blockIdx.y * 96;
    const int n0 = blockIdx.x * 64;

    float acc[2][4][4];
#pragma unroll
    for (int i = 0; i < 2; i++)
#pragma unroll
        for (int j = 0; j < 4; j++)
#pragma unroll
            for (int q = 0; q < 4; q++) acc[i][j][q] = 0.f;

    auto loadStage = [&](int kt, int st) {
        const __half* A = (kt < 16) ? a1 : a2;
        const __half* W = (kt < 16) ? w1 : w2;
        int k0 = (kt & 15) * 32;
        __half* base = dsm + st * STAGE_HALVES;
#pragma unroll
        for (int rep = 0; rep < 2; rep++) {
            int idx = tx + rep * 192;
            int row = idx >> 2;
            int seg = (idx & 3) * 8;
            size_t ao = (size_t)(m0 + row) * HH + k0 + seg;
            uint32_t so = (uint32_t)(row * LDS + seg);
            cpa16(cvta_s(base + so), A + ao);
        }
        {
            int idx = tx;                 // B: 64 rows x 4 segs = 256 slots
            if (idx < 192) {
                int row = idx >> 2;
                int seg = (idx & 3) * 8;
                size_t wo = (size_t)(n0 + row) * HH + k0 + seg;
                cpa16(cvta_s(base + A_HALVES + row * LDS + seg), W + wo);
            }
            idx = tx + 192;
            if (idx < 256) {
                int row = idx >> 2;
                int seg = (idx & 3) * 8;
                size_t wo = (size_t)(n0 + row) * HH + k0 + seg;
                cpa16(cvta_s(base + A_HALVES + row * LDS + seg), W + wo);
            }
        }
        asm volatile("cp.async.commit_group;\n");
    };

    loadStage(0, 0);

    for (int kt = 0; kt < nk; ++kt) {
        int st = kt & 1;
        if (kt + 1 < nk) {
            loadStage(kt + 1, st ^ 1);
            asm volatile("cp.async.wait_group 1;\n" ::: "memory");
        } else {
            asm volatile("cp.async.wait_group 0;\n" ::: "memory");
        }
        __syncthreads();

        __half* base = dsm + st * STAGE_HALVES;
        __half* sA = base;
        __half* sW = base + A_HALVES;

#pragma unroll
        for (int ks = 0; ks < 2; ks++) {
            int kc = ks * 16;
            uint32_t ah[2][4];
#pragma unroll
            for (int i = 0; i < 2; i++) {
                int r = wm + i * 16 + (lane & 15);
                int c = kc + ((lane >> 4) & 1) * 8;
                ldm_x4(ah[i][0], ah[i][1], ah[i][2], ah[i][3], cvta_s(sA + r * LDS + c));
            }
#pragma unroll
            for (int jj = 0; jj < 2; jj++) {
                int r = wn + jj * 16 + (lane & 7) + ((lane >> 4) & 1) * 8;
                int c = kc + ((lane >> 3) & 1) * 8;
                uint32_t bh[4];
                ldm_x4(bh[0], bh[1], bh[2], bh[3], cvta_s(sW + r * LDS + c));
#pragma unroll
                for (int i = 0; i < 2; i++) {
                    mma_f16(acc[i][jj * 2 + 0], ah[i][0], ah[i][1], ah[i][2], ah[i][3], bh[0], bh[1]);
                    mma_f16(acc[i][jj * 2 + 1], ah[i][0], ah[i][1], ah[i][2], ah[i][3], bh[2], bh[3]);
                }
            }
        }
        __syncthreads();
    }

    if (!finalize) {
#pragma unroll
        for (int j = 0; j < 4; j++) {
#pragma unroll
            for (int i = 0; i < 2; i++) {
                int r = m0 + wm + i * 16 + (lane >> 2);
                int c = n0 + wn + j * 8 + (lane & 3) * 2;
                *(float2*)(Cpart + (size_t)r * HH + c) = make_float2(acc[i][j][0], acc[i][j][1]);
                *(float2*)(Cpart + (size_t)(r + 8) * HH + c) = make_float2(acc[i][j][2], acc[i][j][3]);
            }
        }
        return;
    }

    // finalize: (+Cin) + relu + fp16 store + fused BN column stats
#pragma unroll
    for (int j = 0; j < 4; j++) {
        float s0 = 0.f, s1 = 0.f, q0 = 0.f, q1 = 0.f;
#pragma unroll
        for (int i = 0; i < 2; i++) {
            int r = m0 + wm + i * 16 + (lane >> 2);
            int c = n0 + wn + j * 8 + (lane & 3) * 2;
            float v00 = acc[i][j][0], v01 = acc[i][j][1];
            float v10 = acc[i][j][2], v11 = acc[i][j][3];
            if (Cin) {
                float2 p0 = *(const float2*)(Cin + (size_t)r * HH + c);
                float2 p1 = *(const float2*)(Cin + (size_t)(r + 8) * HH + c);
                v00 += p0.x; v01 += p0.y; v10 += p1.x; v11 += p1.y;
            }
            v00 = fmaxf(v00, 0.f); v01 = fmaxf(v01, 0.f);
            v10 = fmaxf(v10, 0.f); v11 = fmaxf(v11, 0.f);
            *(__half2*)(Z + (size_t)r * HH + c) =
                __halves2half2(__float2half(v00), __float2half(v01));
            *(__half2*)(Z + (size_t)(r + 8) * HH + c) =
                __halves2half2(__float2half(v10), __float2half(v11));
            s0 += v00 + v10; s1 += v01 + v11;
            q0 += v00 * v00 + v10 * v10; q1 += v01 * v01 + v11 * v11;
        }
#pragma unroll
        for (int o = 16; o >= 4; o >>= 1) {
            s0 += __shfl_down_sync(0xffffffff, s0, o);
            s1 += __shfl_down_sync(0xffffffff, s1, o);
            q0 += __shfl_down_sync(0xffffffff, q0, o);
            q1 += __shfl_down_sync(0xffffffff, q1, o);
        }
        if (lane < 4) {
            int cc = n0 + wn + j * 8 + lane * 2;
            atomicAdd(&g_sum[cc], s0);
            atomicAdd(&g_sum[cc + 1], s1);
            atomicAdd(&g_sq[cc], q0);
            atomicAdd(&g_sq[cc + 1], q1);
        }
    }
}

// ---------------- BatchNorm finalize (reads + self-zeroes stats) ----------------
__global__ void k_bnfin(const float* __restrict__ gamma, const float* __restrict__ beta) {
    int f = threadIdx.x;
    float s = g_sum[f];
    float q = g_sq[f];
    g_sum[f] = 0.f;
    g_sq[f] = 0.f;
    float mu = s / (float)NN;
    float var = q / (float)NN - mu * mu;
    float inv = rsqrtf(var + BN_EPS);
    float sc = gamma[f] * inv;
    g_bnA[f] = sc;
    g_bnB[f] = beta[f] - mu * sc;
}

// ---------------- final conv (C=10) + log_softmax ----------------
__global__ __launch_bounds__(320)
void k_final(const float* __restrict__ agg, const __half* __restrict__ r,
             const float* __restrict__ Wr, const float* __restrict__ Ww,
             float* __restrict__ out) {
    __shared__ float sa[HH];
    __shared__ float sh[HH];
    __shared__ float slog[CC];
    __shared__ float sLse;
    int node = blockIdx.x;
    int t = threadIdx.x;
    for (int i = t; i < HH; i += 320) {
        sa[i] = agg[(size_t)node * HH + i];
        sh[i] = __half2float(r[(size_t)node * HH + i]) * g_bnA[i] + g_bnB[i];
    }
    __syncthreads();
    int w = t >> 5, lane = t & 31;
    float s = 0.f;
    for (int k = lane; k < HH; k += 32)
        s += sa[k] * Wr[w * HH + k] + sh[k] * Ww[w * HH + k];
#pragma unroll
    for (int o = 16; o; o >>= 1) s += __shfl_down_sync(0xffffffff, s, o);
    if (lane == 0) slog[w] = s;
    __syncthreads();
    if (t == 0) {
        float mx = slog[0];
        for (int c = 1; c < CC; c++) mx = fmaxf(mx, slog[c]);
        float sum = 0.f;
        for (int c = 0; c < CC; c++) sum += expf(slog[c] - mx);
        sLse = mx + logf(sum);
    }
    __syncthreads();
    if (t < CC) out[(size_t)node * CC + t] = slog[t] - sLse;
}

// ---------------- launch ----------------
extern "C" void kernel_launch(void* const* d_in, const int* in_sizes, int n_in,
                              void* d_out, int out_size) {
    const float* x     = (const float*)d_in[0];
    const int*   ei    = (const int*)d_in[1];
    const float* Wpr   = (const float*)d_in[2];
    const float* Wpw   = (const float*)d_in[3];
    const float* Wrel  = (const float*)d_in[4];
    const float* Wroot = (const float*)d_in[5];
    const float* gamma = (const float*)d_in[6];
    const float* beta  = (const float*)d_in[7];
    const float* Wfr   = (const float*)d_in[8];
    const float* Wfw   = (const float*)d_in[9];
    float* out = (float*)d_out;

    static float *p_part = nullptr, *p_agg = nullptr;
    static __half *p_z1, *p_z2, *p_x16, *p_h16, *p_a16, *p_w;
    if (!p_part) {
        cudaGetSymbolAddress((void**)&p_part, g_part);
        cudaGetSymbolAddress((void**)&p_agg, g_agg);
        cudaGetSymbolAddress((void**)&p_z1, g_z1);
        cudaGetSymbolAddress((void**)&p_z2, g_z2);
        cudaGetSymbolAddress((void**)&p_x16, g_x16);
        cudaGetSymbolAddress((void**)&p_h16, g_h16);
        cudaGetSymbolAddress((void**)&p_a16, g_a16);
        cudaGetSymbolAddress((void**)&p_w, g_w);
    }

    dim3 gemmGrid(HH / 64, NP / 96);    // (8, 106) = 848 CTAs
    int eb = (EE + 255) / 256;
    int prepb = (PREP_TOTAL + 255) / 256;

    // 1: deg, 2: prep, 3: scan+scale, 4: GEMM(root half of proj) <- profiled window
    k_deg<<<eb, 256>>>(ei);
    k_prep<<<prepb, 256>>>(x, Wpr, Wpw, Wrel, Wroot);
    k_scanscale<<<1, 1024>>>();
    k_gemm9<<<gemmGrid, 192>>>(p_x16, p_x16,
                               p_w + 1 * MM, p_w + 1 * MM,
                               p_part, nullptr, nullptr, 16, 0);  // x@Wpw^T
    // 5: fill, 6: agg(x fp16), 7: GEMM(rel half, finalize -> z1 fp16 + stats)
    k_fill<<<eb, 256>>>(ei);
    k_agg3<<<NN, 128>>>(p_x16, 0, p_a16, nullptr, nullptr);
    k_gemm9<<<gemmGrid, 192>>>(p_a16, p_a16,
                               p_w + 0 * MM, p_w + 0 * MM,
                               nullptr, p_part, p_z1, 16, 1);
    k_bnfin<<<1, HH>>>(gamma, beta);

    __half* cur = p_z1;
    __half* nxt = p_z2;
    for (int l = 0; l < 3; ++l) {
        // agg of BN'd z (mean commutes with affine) + fused own-row BN -> h16
        k_agg3<<<NN, 128>>>(cur, 1, p_a16, nullptr, p_h16);
        k_gemm9<<<gemmGrid, 192>>>(p_a16, p_h16,
                                   p_w + (2 + l) * MM, p_w + (5 + l) * MM,
                                   nullptr, nullptr, nxt, 32, 1);
        k_bnfin<<<1, HH>>>(gamma + (size_t)(l + 1) * HH, beta + (size_t)(l + 1) * HH);
        __half* tmp = cur; cur = nxt; nxt = tmp;
    }

    // final conv + log_softmax (agg BN'd in k_agg3; root row BN'd in k_final)
    k_agg3<<<NN, 128>>>(cur, 1, nullptr, p_agg, nullptr);
    k_final<<<NN, 320>>>(p_agg, cur, Wfr, Wfw, out);
}

// round 15
// speedup vs baseline: 1.1287x; 1.1287x over previous
#include <cuda_runtime.h>
#include <cuda_fp16.h>
#include <math.h>
#include <stdint.h>

#define NN 10000
#define NP 10176            // 106 * 96
#define EE 160000
#define HH 512
#define CC 10
#define MM (HH * HH)
#define BN_EPS 1e-5f

// ---------------- device scratch ----------------
__device__ float  g_agg[NP * HH];    // fp32 BN'd agg for final layer
__device__ __half g_z1[NP * HH];     // raw relu z fp16 (ping)
__device__ __half g_z2[NP * HH];     // raw relu z fp16 (pong)
__device__ __half g_x16[NP * HH];    // x fp16
__device__ __half g_h16[NP * HH];    // BN(z) fp16 (root operand)
__device__ __half g_a16[NP * HH];    // agg fp16
__device__ __half g_w[8 * MM];       // weights fp16 (Wpr, Wpw, Wrel0-2, Wroot0-2)
__device__ float g_scale[NN];
__device__ int   g_degi[NN];         // zeroed per-node inside k_agg3
__device__ int   g_rowptr[NN + 1];
__device__ int   g_fill[NN];
__device__ int   g_esrc[EE];
__device__ float g_sum[HH];
__device__ float g_sq[HH];
__device__ float g_bnA[HH];
__device__ float g_bnB[HH];

// ---------------- PTX helpers ----------------
__device__ __forceinline__ uint32_t cvta_s(const void* p) {
    return (uint32_t)__cvta_generic_to_shared(p);
}
__device__ __forceinline__ void cpa16(uint32_t dst, const void* src) {
    asm volatile("cp.async.cg.shared.global [%0], [%1], 16;\n" :: "r"(dst), "l"(src));
}
__device__ __forceinline__ void ldm_x4(uint32_t& r0, uint32_t& r1, uint32_t& r2, uint32_t& r3, uint32_t addr) {
    asm volatile("ldmatrix.sync.aligned.m8n8.x4.shared.b16 {%0,%1,%2,%3}, [%4];\n"
                 : "=r"(r0), "=r"(r1), "=r"(r2), "=r"(r3) : "r"(addr));
}
__device__ __forceinline__ void mma_f16(float* d, uint32_t a0, uint32_t a1, uint32_t a2, uint32_t a3,
                                        uint32_t b0, uint32_t b1) {
    asm volatile("mma.sync.aligned.m16n8k16.row.col.f32.f16.f16.f32 "
                 "{%0,%1,%2,%3}, {%4,%5,%6,%7}, {%8,%9}, {%0,%1,%2,%3};\n"
                 : "+f"(d[0]), "+f"(d[1]), "+f"(d[2]), "+f"(d[3])
                 : "r"(a0), "r"(a1), "r"(a2), "r"(a3), "r"(b0), "r"(b1));
}

// ---------------- fused prep: pads, x round, weight round, stats zero --------
#define SPLITX (NN * HH)
#define SPLITW (8 * MM)
#define PADSZ  ((NP - NN) * HH)
#define PREP_TOTAL (SPLITX + SPLITW + PADSZ + HH)

__global__ void k_prep(const float* __restrict__ x,
                       const float* __restrict__ Wpr, const float* __restrict__ Wpw,
                       const float* __restrict__ Wrel, const float* __restrict__ Wroot) {
    int i = blockIdx.x * blockDim.x + threadIdx.x;
    if (i < SPLITX) {
        g_x16[i] = __float2half(x[i]);
        return;
    }
    i -= SPLITX;
    if (i < SPLITW) {
        int w = i >> 18;
        int off = i & (MM - 1);
        const float* src;
        if (w == 0) src = Wpr + off;
        else if (w == 1) src = Wpw + off;
        else if (w < 5) src = Wrel + (size_t)(w - 2) * MM + off;
        else src = Wroot + (size_t)(w - 5) * MM + off;
        g_w[i] = __float2half(*src);
        return;
    }
    i -= SPLITW;
    if (i < PADSZ) {
        int off = NN * HH + i;
        __half z = __float2half(0.0f);
        g_x16[off] = z;
        g_h16[off] = z;
        g_a16[off] = z;
        return;
    }
    i -= PADSZ;
    if (i < HH) { g_sum[i] = 0.f; g_sq[i] = 0.f; }
}

// ---------------- CSR build ----------------
__global__ void k_deg(const int* __restrict__ ei) {
    int e = blockIdx.x * blockDim.x + threadIdx.x;
    if (e < EE) atomicAdd(&g_degi[ei[EE + e]], 1);
}
__global__ void k_scanscale() {
    __shared__ int warp_part[32];
    __shared__ int carry;
    int t = threadIdx.x;
    int lane = t & 31, w = t >> 5;
    if (t == 0) carry = 0;
    __syncthreads();
    for (int base = 0; base < NN; base += 1024) {
        int i = base + t;
        int v = (i < NN) ? g_degi[i] : 0;
        if (i < NN) g_scale[i] = 1.0f / (float)(v > 0 ? v : 1);
        int s = v;
#pragma unroll
        for (int o = 1; o < 32; o <<= 1) {
            int u = __shfl_up_sync(0xffffffff, s, o);
            if (lane >= o) s += u;
        }
        if (lane == 31) warp_part[w] = s;
        __syncthreads();
        if (w == 0) {
            int p = warp_part[lane];
#pragma unroll
            for (int o = 1; o < 32; o <<= 1) {
                int u = __shfl_up_sync(0xffffffff, p, o);
                if (lane >= o) p += u;
            }
            warp_part[lane] = p;
        }
        __syncthreads();
        int add = (w > 0) ? warp_part[w - 1] : 0;
        int inc = s + add + carry;
        if (i < NN) g_rowptr[i + 1] = inc;
        __syncthreads();
        if (t == 1023) carry = inc;
        __syncthreads();
    }
    if (t == 0) g_rowptr[0] = 0;
}
__global__ void k_fill(const int* __restrict__ ei) {
    int e = blockIdx.x * blockDim.x + threadIdx.x;
    if (e < EE) {
        int dst = ei[EE + e];
        int pos = g_rowptr[dst] + atomicAdd(&g_fill[dst], 1);
        g_esrc[pos] = ei[e];
    }
}

// ---------------- fp16 mean aggregation + BN affine + fused own-row BN ----------------
// If ownbn != nullptr: also write h16[node] = bnA*z[node]+bnB (replaces bnapply).
__global__ void k_agg3(const __half* __restrict__ z, int useBN,
                       __half* __restrict__ oh, float* __restrict__ of,
                       __half* __restrict__ ownbn) {
    int node = blockIdx.x;
    int t = threadIdx.x;                   // 0..127, 4 halves each
    if (t == 0) { g_degi[node] = 0; g_fill[node] = 0; }   // reset for next replay
    int s = g_rowptr[node];
    int e = g_rowptr[node + 1];
    float ax = 0.f, ay = 0.f, az = 0.f, aw = 0.f;
    int j = s;
    for (; j + 1 < e; j += 2) {
        int s0 = g_esrc[j];
        int s1 = g_esrc[j + 1];
        uint2 r0 = ((const uint2*)(z + (size_t)s0 * HH))[t];
        uint2 r1 = ((const uint2*)(z + (size_t)s1 * HH))[t];
        float2 a0 = __half22float2(*(__half2*)&r0.x);
        float2 a1 = __half22float2(*(__half2*)&r0.y);
        float2 b0 = __half22float2(*(__half2*)&r1.x);
        float2 b1 = __half22float2(*(__half2*)&r1.y);
        ax += a0.x + b0.x; ay += a0.y + b0.y;
        az += a1.x + b1.x; aw += a1.y + b1.y;
    }
    if (j < e) {
        int s0 = g_esrc[j];
        uint2 r0 = ((const uint2*)(z + (size_t)s0 * HH))[t];
        float2 a0 = __half22float2(*(__half2*)&r0.x);
        float2 a1 = __half22float2(*(__half2*)&r0.y);
        ax += a0.x; ay += a0.y; az += a1.x; aw += a1.y;
    }
    float sc = g_scale[node];
    ax *= sc; ay *= sc; az *= sc; aw *= sc;
    float4 a, b;
    if (useBN) {
        a = ((const float4*)g_bnA)[t];
        b = ((const float4*)g_bnB)[t];
        ax = ax * a.x + b.x; ay = ay * a.y + b.y;
        az = az * a.z + b.z; aw = aw * a.w + b.w;
    }
    if (of) {
        ((float4*)(of + (size_t)node * HH))[t] = make_float4(ax, ay, az, aw);
    }
    if (oh) {
        __half2* ph = (__half2*)(oh + (size_t)node * HH);
        ph[t * 2 + 0] = __halves2half2(__float2half(ax), __float2half(ay));
        ph[t * 2 + 1] = __halves2half2(__float2half(az), __float2half(aw));
    }
    if (ownbn) {
        uint2 raw = ((const uint2*)(z + (size_t)node * HH))[t];
        float2 v0 = __half22float2(*(__half2*)&raw.x);
        float2 v1 = __half22float2(*(__half2*)&raw.y);
        v0.x = v0.x * a.x + b.x;
        v0.y = v0.y * a.y + b.y;
        v1.x = v1.x * a.z + b.z;
        v1.y = v1.y * a.w + b.w;
        __half2* po = (__half2*)(ownbn + (size_t)node * HH);
        po[t * 2 + 0] = __halves2half2(__float2half(v0.x), __float2half(v0.y));
        po[t * 2 + 1] = __halves2half2(__float2half(v1.x), __float2half(v1.y));
    }
}

// ---------------- mma.sync dual GEMM, 96x128 tile, BK=32, fp16 (R13-proven) -----
// acc = A1@W1^T (kt<16) + A2@W2^T (kt>=16); relu -> fp16 Z + fused BN stats.
#define LDS 40
#define A_HALVES (96 * LDS)                       // 3840
#define B_HALVES (128 * LDS)                      // 5120
#define STAGE_HALVES (A_HALVES + B_HALVES)        // 8960 halves = 17920 B
#define GEMM_SMEM (2 * STAGE_HALVES * 2)          // 35840 B

__global__ __launch_bounds__(192, 3)
void k_gemm8(const __half* __restrict__ a1, const __half* __restrict__ a2,
             const __half* __restrict__ w1, const __half* __restrict__ w2,
             __half* __restrict__ Z) {
    extern __shared__ __half dsm[];

    const int tx = threadIdx.x;
    const int lane = tx & 31;
    const int warp = tx >> 5;
    const int wm = (warp % 3) * 32;
    const int wn = (warp / 3) * 64;
    const int m0 = blockIdx.y * 96;
    const int n0 = blockIdx.x * 128;

    float acc[2][8][4];
#pragma unroll
    for (int i = 0; i < 2; i++)
#pragma unroll
        for (int j = 0; j < 8; j++)
#pragma unroll
            for (int q = 0; q < 4; q++) acc[i][j][q] = 0.f;

    auto loadStage = [&](int kt, int st) {
        const __half* A = (kt < 16) ? a1 : a2;
        const __half* W = (kt < 16) ? w1 : w2;
        int k0 = (kt & 15) * 32;
        __half* base = dsm + st * STAGE_HALVES;
#pragma unroll
        for (int rep = 0; rep < 2; rep++) {
            int idx = tx + rep * 192;
            int row = idx >> 2;
            int seg = (idx & 3) * 8;
            size_t ao = (size_t)(m0 + row) * HH + k0 + seg;
            uint32_t so = (uint32_t)(row * LDS + seg);
            cpa16(cvta_s(base + so), A + ao);
        }
#pragma unroll
        for (int rep = 0; rep < 3; rep++) {
            int idx = tx + rep * 192;
            if (idx < 512) {
                int row = idx >> 2;
                int seg = (idx & 3) * 8;
                size_t wo = (size_t)(n0 + row) * HH + k0 + seg;
                uint32_t so = (uint32_t)(row * LDS + seg);
                cpa16(cvta_s(base + A_HALVES + so), W + wo);
            }
        }
        asm volatile("cp.async.commit_group;\n");
    };

    loadStage(0, 0);

    const int NK = 32;
    for (int kt = 0; kt < NK; ++kt) {
        int st = kt & 1;
        if (kt + 1 < NK) {
            loadStage(kt + 1, st ^ 1);
            asm volatile("cp.async.wait_group 1;\n" ::: "memory");
        } else {
            asm volatile("cp.async.wait_group 0;\n" ::: "memory");
        }
        __syncthreads();

        __half* base = dsm + st * STAGE_HALVES;
        __half* sA = base;
        __half* sW = base + A_HALVES;

#pragma unroll
        for (int ks = 0; ks < 2; ks++) {
            int kc = ks * 16;
            uint32_t ah[2][4];
#pragma unroll
            for (int i = 0; i < 2; i++) {
                int r = wm + i * 16 + (lane & 15);
                int c = kc + ((lane >> 4) & 1) * 8;
                ldm_x4(ah[i][0], ah[i][1], ah[i][2], ah[i][3], cvta_s(sA + r * LDS + c));
            }
#pragma unroll
            for (int jj = 0; jj < 4; jj++) {
                int r = wn + jj * 16 + (lane & 7) + ((lane >> 4) & 1) * 8;
                int c = kc + ((lane >> 3) & 1) * 8;
                uint32_t bh[4];
                ldm_x4(bh[0], bh[1], bh[2], bh[3], cvta_s(sW + r * LDS + c));
#pragma unroll
                for (int i = 0; i < 2; i++) {
                    mma_f16(acc[i][jj * 2 + 0], ah[i][0], ah[i][1], ah[i][2], ah[i][3], bh[0], bh[1]);
                    mma_f16(acc[i][jj * 2 + 1], ah[i][0], ah[i][1], ah[i][2], ah[i][3], bh[2], bh[3]);
                }
            }
        }
        __syncthreads();
    }

    // epilogue: relu + fp16 store + fused BN column stats
#pragma unroll
    for (int j = 0; j < 8; j++) {
        float s0 = 0.f, s1 = 0.f, q0 = 0.f, q1 = 0.f;
#pragma unroll
        for (int i = 0; i < 2; i++) {
            int r = m0 + wm + i * 16 + (lane >> 2);
            int c = n0 + wn + j * 8 + (lane & 3) * 2;
            float v00 = fmaxf(acc[i][j][0], 0.f), v01 = fmaxf(acc[i][j][1], 0.f);
            float v10 = fmaxf(acc[i][j][2], 0.f), v11 = fmaxf(acc[i][j][3], 0.f);
            *(__half2*)(Z + (size_t)r * HH + c) =
                __halves2half2(__float2half(v00), __float2half(v01));
            *(__half2*)(Z + (size_t)(r + 8) * HH + c) =
                __halves2half2(__float2half(v10), __float2half(v11));
            s0 += v00 + v10; s1 += v01 + v11;
            q0 += v00 * v00 + v10 * v10; q1 += v01 * v01 + v11 * v11;
        }
#pragma unroll
        for (int o = 16; o >= 4; o >>= 1) {
            s0 += __shfl_down_sync(0xffffffff, s0, o);
            s1 += __shfl_down_sync(0xffffffff, s1, o);
            q0 += __shfl_down_sync(0xffffffff, q0, o);
            q1 += __shfl_down_sync(0xffffffff, q1, o);
        }
        if (lane < 4) {
            int cc = n0 + wn + j * 8 + lane * 2;
            atomicAdd(&g_sum[cc], s0);
            atomicAdd(&g_sum[cc + 1], s1);
            atomicAdd(&g_sq[cc], q0);
            atomicAdd(&g_sq[cc + 1], q1);
        }
    }
}

// ---------------- BatchNorm finalize (reads + self-zeroes stats) ----------------
__global__ void k_bnfin(const float* __restrict__ gamma, const float* __restrict__ beta) {
    int f = threadIdx.x;
    float s = g_sum[f];
    float q = g_sq[f];
    g_sum[f] = 0.f;
    g_sq[f] = 0.f;
    float mu = s / (float)NN;
    float var = q / (float)NN - mu * mu;
    float inv = rsqrtf(var + BN_EPS);
    float sc = gamma[f] * inv;
    g_bnA[f] = sc;
    g_bnB[f] = beta[f] - mu * sc;
}

// ---------------- final conv (C=10) + log_softmax ----------------
__global__ __launch_bounds__(320)
void k_final(const float* __restrict__ agg, const __half* __restrict__ r,
             const float* __restrict__ Wr, const float* __restrict__ Ww,
             float* __restrict__ out) {
    __shared__ float sa[HH];
    __shared__ float sh[HH];
    __shared__ float slog[CC];
    __shared__ float sLse;
    int node = blockIdx.x;
    int t = threadIdx.x;
    for (int i = t; i < HH; i += 320) {
        sa[i] = agg[(size_t)node * HH + i];
        sh[i] = __half2float(r[(size_t)node * HH + i]) * g_bnA[i] + g_bnB[i];
    }
    __syncthreads();
    int w = t >> 5, lane = t & 31;
    float s = 0.f;
    for (int k = lane; k < HH; k += 32)
        s += sa[k] * Wr[w * HH + k] + sh[k] * Ww[w * HH + k];
#pragma unroll
    for (int o = 16; o; o >>= 1) s += __shfl_down_sync(0xffffffff, s, o);
    if (lane == 0) slog[w] = s;
    __syncthreads();
    if (t == 0) {
        float mx = slog[0];
        for (int c = 1; c < CC; c++) mx = fmaxf(mx, slog[c]);
        float sum = 0.f;
        for (int c = 0; c < CC; c++) sum += expf(slog[c] - mx);
        sLse = mx + logf(sum);
    }
    __syncthreads();
    if (t < CC) out[(size_t)node * CC + t] = slog[t] - sLse;
}

// ---------------- launch ----------------
extern "C" void kernel_launch(void* const* d_in, const int* in_sizes, int n_in,
                              void* d_out, int out_size) {
    const float* x     = (const float*)d_in[0];
    const int*   ei    = (const int*)d_in[1];
    const float* Wpr   = (const float*)d_in[2];
    const float* Wpw   = (const float*)d_in[3];
    const float* Wrel  = (const float*)d_in[4];
    const float* Wroot = (const float*)d_in[5];
    const float* gamma = (const float*)d_in[6];
    const float* beta  = (const float*)d_in[7];
    const float* Wfr   = (const float*)d_in[8];
    const float* Wfw   = (const float*)d_in[9];
    float* out = (float*)d_out;

    static float *p_agg = nullptr;
    static __half *p_z1, *p_z2, *p_x16, *p_h16, *p_a16, *p_w;
    if (!p_agg) {
        cudaGetSymbolAddress((void**)&p_agg, g_agg);
        cudaGetSymbolAddress((void**)&p_z1, g_z1);
        cudaGetSymbolAddress((void**)&p_z2, g_z2);
        cudaGetSymbolAddress((void**)&p_x16, g_x16);
        cudaGetSymbolAddress((void**)&p_h16, g_h16);
        cudaGetSymbolAddress((void**)&p_a16, g_a16);
        cudaGetSymbolAddress((void**)&p_w, g_w);
        cudaFuncSetAttribute(k_gemm8, cudaFuncAttributeMaxDynamicSharedMemorySize, GEMM_SMEM);
    }

    dim3 gemmGrid(HH / 128, NP / 96);   // (4, 106) = 424 CTAs
    int eb = (EE + 255) / 256;
    int prepb = (PREP_TOTAL + 255) / 256;

    // CSR + prep
    k_deg<<<eb, 256>>>(ei);
    k_prep<<<prepb, 256>>>(x, Wpr, Wpw, Wrel, Wroot);
    k_scanscale<<<1, 1024>>>();
    k_fill<<<eb, 256>>>(ei);

    // proj layer: single dual GEMM  z1 = relu(agg(x)@Wpr^T + x@Wpw^T)
    k_agg3<<<NN, 128>>>(p_x16, 0, p_a16, nullptr, nullptr);
    k_gemm8<<<gemmGrid, 192, GEMM_SMEM>>>(p_a16, p_x16,
                                          p_w + 0 * MM, p_w + 1 * MM, p_z1);
    k_bnfin<<<1, HH>>>(gamma, beta);

    __half* cur = p_z1;
    __half* nxt = p_z2;
    for (int l = 0; l < 3; ++l) {
        // agg of BN'd z (mean commutes with affine) + fused own-row BN -> h16
        k_agg3<<<NN, 128>>>(cur, 1, p_a16, nullptr, p_h16);
        k_gemm8<<<gemmGrid, 192, GEMM_SMEM>>>(p_a16, p_h16,
                                              p_w + (2 + l) * MM, p_w + (5 + l) * MM, nxt);
        k_bnfin<<<1, HH>>>(gamma + (size_t)(l + 1) * HH, beta + (size_t)(l + 1) * HH);
        __half* tmp = cur; cur = nxt; nxt = tmp;
    }

    // final conv + log_softmax (agg BN'd in k_agg3; root row BN'd in k_final)
    k_agg3<<<NN, 128>>>(cur, 1, nullptr, p_agg, nullptr);
    k_final<<<NN, 320>>>(p_agg, cur, Wfr, Wfw, out);
}